// round 6
// baseline (speedup 1.0000x reference)
#include <cuda_runtime.h>

#define Wd 256
#define Hd 256
#define Bd 64
#define NPIX (Bd*Hd*Wd)
#define QIMG 16
#define QPIX (QIMG*Hd*Wd)   // per-quarter pixels (4MB/field)
#define NVQ  (QPIX/4)
#define EPSf 1e-12f

// ---- iteration-invariant scratch ----
__device__ __align__(16) float g_g2x[NPIX];
__device__ __align__(16) float g_g2y[NPIX];
__device__ __align__(16) float g_rc [NPIX];
// ---- double-buffered dual state ----
__device__ __align__(16) float g_p11[2][NPIX];
__device__ __align__(16) float g_p12[2][NPIX];
__device__ __align__(16) float g_p21[2][NPIX];
__device__ __align__(16) float g_p22[2][NPIX];
// ---- u scratch (ping-pongs with d_out) ----
__device__ __align__(16) float g_u1s[NPIX];
__device__ __align__(16) float g_u2s[NPIX];

union F4 { float4 v; float f[4]; };

__device__ __forceinline__ float4 ld4(const float* p) { return *reinterpret_cast<const float4*>(p); }
__device__ __forceinline__ void   st4(float* p, float4 v) { *reinterpret_cast<float4*>(p) = v; }

// p' = (p + taut*grad_u) / (1 + taut*|grad_u|)  (one pixel, both flow comps)
__device__ __forceinline__ void p_lane(
    float uC1, float uR1, float uD1, float uC2, float uR2, float uD2,
    bool hasR, bool hasD, float taut,
    float p11, float p12, float p21, float p22,
    float& o11, float& o12, float& o21, float& o22)
{
    float u1x = hasR ? (uR1 - uC1) : 0.f;
    float u2x = hasR ? (uR2 - uC2) : 0.f;
    float u1y = hasD ? (uD1 - uC1) : 0.f;
    float u2y = hasD ? (uD2 - uC2) : 0.f;
    float n1 = sqrtf(u1x*u1x + u1y*u1y + EPSf);
    float n2 = sqrtf(u2x*u2x + u2y*u2y + EPSf);
    float f1 = 1.0f / (1.0f + taut * n1);
    float f2 = 1.0f / (1.0f + taut * n2);
    o11 = (p11 + taut * u1x) * f1;
    o12 = (p12 + taut * u1y) * f1;
    o21 = (p21 + taut * u2x) * f2;
    o22 = (p22 + taut * u2y) * f2;
}

// u' = u + v(u) + ts*div(p)
__device__ __forceinline__ void u_lane(
    float u1, float u2, float gx, float gy, float rc,
    float p11, float p11L, float p12, float p12U,
    float p21, float p21L, float p22, float p22U,
    bool j0, bool i0, float ts, float l_t,
    float& o1, float& o2)
{
    float dx1 = j0 ? p11 : (p11 - p11L);
    float dx2 = j0 ? p21 : (p21 - p21L);
    float dy1 = i0 ? p12 : (p12 - p12U);
    float dy2 = i0 ? p22 : (p22 - p22U);
    float rho  = rc + gx * u1 + gy * u2 + EPSf;
    float grad = gx * gx + gy * gy + EPSf;
    float lg   = l_t * grad;
    float v1, v2;
    if      (rho < -lg)   { v1 =  l_t * gx; v2 =  l_t * gy; }
    else if (rho >  lg)   { v1 = -l_t * gx; v2 = -l_t * gy; }
    else if (grad > EPSf) { float s = -rho / grad; v1 = s * gx; v2 = s * gy; }
    else                  { v1 = 0.f; v2 = 0.f; }
    o1 = u1 + v1 + ts * (dx1 + dy1);
    o2 = u2 + v2 + ts * (dx2 + dy2);
}

// ============================================================================
// Init (per quarter): g2x, g2y, rc = y-x, iteration-1 u (u=0, p=0).
// ============================================================================
__global__ void __launch_bounds__(256) k_init(
    const float* __restrict__ x, const float* __restrict__ y,
    const float* __restrict__ tp, const float* __restrict__ lp,
    float* __restrict__ u1, float* __restrict__ u2, int off)
{
    int v = blockIdx.x * blockDim.x + threadIdx.x;
    if (v >= NVQ) return;
    int il = v << 2;
    int idx = il + off;
    int j4 = il & (Wd - 1);
    int i  = (il >> 8) & (Hd - 1);

    float ts  = tp[0];
    float l_t = lp[0] * ts;

    F4 X, Y, Yu, Yd, Xu, Xd;
    X.v = ld4(x + idx);
    Y.v = ld4(y + idx);
    float yl = (j4 > 0)       ? y[idx - 1] : 0.f;
    float yr = (j4 + 4 < Wd)  ? y[idx + 4] : 0.f;
    Yu.v = (i > 0)      ? ld4(y + idx - Wd) : make_float4(0,0,0,0);
    Yd.v = (i < Hd - 1) ? ld4(y + idx + Wd) : make_float4(0,0,0,0);
    Xd.v = (i == 0)      ? ld4(x + idx + Wd) : make_float4(0,0,0,0);
    Xu.v = (i == Hd - 1) ? ld4(x + idx - Wd) : make_float4(0,0,0,0);

    F4 GX, GY, RC, O1, O2;
#pragma unroll
    for (int k = 0; k < 4; k++) {
        int j = j4 + k;
        float gx;
        if (j == 0)            gx = 0.5f * (X.f[1] - X.f[0]);
        else if (j == Wd - 1)  gx = 0.5f * (X.f[3] - X.f[2]);
        else {
            float yn = (k < 3) ? Y.f[k + 1] : yr;
            float yp = (k > 0) ? Y.f[k - 1] : yl;
            gx = 0.5f * (yn - yp);
        }
        float gy;
        if (i == 0)            gy = 0.5f * (Xd.f[k] - X.f[k]);
        else if (i == Hd - 1)  gy = 0.5f * (X.f[k] - Xu.f[k]);
        else                   gy = 0.5f * (Yd.f[k] - Yu.f[k]);

        float rc = Y.f[k] - X.f[k];
        GX.f[k] = gx; GY.f[k] = gy; RC.f[k] = rc;

        float rho  = rc + EPSf;
        float grad = gx * gx + gy * gy + EPSf;
        float lg   = l_t * grad;
        float v1, v2;
        if      (rho < -lg)   { v1 =  l_t * gx; v2 =  l_t * gy; }
        else if (rho >  lg)   { v1 = -l_t * gx; v2 = -l_t * gy; }
        else if (grad > EPSf) { float s = -rho / grad; v1 = s * gx; v2 = s * gy; }
        else                  { v1 = 0.f; v2 = 0.f; }
        O1.f[k] = v1; O2.f[k] = v2;
    }
    st4(g_g2x + idx, GX.v);
    st4(g_g2y + idx, GY.v);
    st4(g_rc  + idx, RC.v);
    st4(u1 + idx, O1.v);
    st4(u2 + idx, O2.v);
}

// ============================================================================
// Fused (P_k, U_{k+1}) — race-free via double buffering + register halo
// recompute of p_new at the left scalar and up vector. No shared memory.
// Reads u from (u1r,u2r) and p_old from set PRD; writes p_new to set PWR
// (skipped if LAST) and u_new to (u1w,u2w).
// ============================================================================
template<bool FIRST, bool LAST, int PRD, int PWR>
__global__ void __launch_bounds__(256) k_pu(
    const float* __restrict__ tp, const float* __restrict__ lp,
    const float* __restrict__ ap,
    const float* __restrict__ u1r, const float* __restrict__ u2r,
    float* __restrict__ u1w, float* __restrict__ u2w, int off)
{
    int v = blockIdx.x * blockDim.x + threadIdx.x;
    if (v >= NVQ) return;
    int il = v << 2;
    int idx = il + off;
    int j4 = il & (Wd - 1);
    int i  = (il >> 8) & (Hd - 1);

    const bool hasU = (i > 0);
    const bool hasD = (i < Hd - 1);
    const bool hasL = (j4 > 0);
    const bool hasRv = (j4 + 4 < Wd);

    const float ts   = tp[0];
    const float l_t  = lp[0] * ts;
    const float taut = ap[0] / ts;

    // ---- u loads ----
    F4 U1c, U2c, U1d, U2d, U1u, U2u;
    U1c.v = ld4(u1r + idx);
    U2c.v = ld4(u2r + idx);
    U1d.v = hasD ? ld4(u1r + idx + Wd) : make_float4(0,0,0,0);
    U2d.v = hasD ? ld4(u2r + idx + Wd) : make_float4(0,0,0,0);
    U1u.v = hasU ? ld4(u1r + idx - Wd) : make_float4(0,0,0,0);
    U2u.v = hasU ? ld4(u2r + idx - Wd) : make_float4(0,0,0,0);
    float u1R  = hasRv ? u1r[idx + 4] : 0.f;                       // right scalar
    float u2R  = hasRv ? u2r[idx + 4] : 0.f;
    float u1UR = (hasU && hasRv) ? u1r[idx - Wd + 4] : 0.f;        // up-right scalar
    float u2UR = (hasU && hasRv) ? u2r[idx - Wd + 4] : 0.f;
    float u1L  = hasL ? u1r[idx - 1] : 0.f;                        // left scalar
    float u2L  = hasL ? u2r[idx - 1] : 0.f;
    float u1DL = (hasL && hasD) ? u1r[idx + Wd - 1] : 0.f;         // down-left scalar
    float u2DL = (hasL && hasD) ? u2r[idx + Wd - 1] : 0.f;

    // ---- p_old loads ----
    F4 P11o, P12o, P21o, P22o, P12uo, P22uo;
    float p11Lo = 0.f, p21Lo = 0.f;
    if (!FIRST) {
        P11o.v = ld4(g_p11[PRD] + idx);
        P12o.v = ld4(g_p12[PRD] + idx);
        P21o.v = ld4(g_p21[PRD] + idx);
        P22o.v = ld4(g_p22[PRD] + idx);
        P12uo.v = hasU ? ld4(g_p12[PRD] + idx - Wd) : make_float4(0,0,0,0);
        P22uo.v = hasU ? ld4(g_p22[PRD] + idx - Wd) : make_float4(0,0,0,0);
        p11Lo = hasL ? g_p11[PRD][idx - 1] : 0.f;
        p21Lo = hasL ? g_p21[PRD][idx - 1] : 0.f;
    } else {
        P11o.v = P12o.v = P21o.v = P22o.v = make_float4(0,0,0,0);
        P12uo.v = P22uo.v = make_float4(0,0,0,0);
    }

    // ---- g loads ----
    F4 GX, GY, RC;
    GX.v = ld4(g_g2x + idx);
    GY.v = ld4(g_g2y + idx);
    RC.v = ld4(g_rc  + idx);

    // ---- p_new at center vector ----
    F4 N11, N12, N21, N22;
#pragma unroll
    for (int k = 0; k < 4; k++) {
        int j = j4 + k;
        float uR1 = (k < 3) ? U1c.f[k+1] : u1R;
        float uR2 = (k < 3) ? U2c.f[k+1] : u2R;
        p_lane(U1c.f[k], uR1, U1d.f[k], U2c.f[k], uR2, U2d.f[k],
               (j < Wd - 1), hasD, taut,
               P11o.f[k], P12o.f[k], P21o.f[k], P22o.f[k],
               N11.f[k], N12.f[k], N21.f[k], N22.f[k]);
    }
    if (!LAST) {
        st4(g_p11[PWR] + idx, N11.v);
        st4(g_p12[PWR] + idx, N12.v);
        st4(g_p21[PWR] + idx, N21.v);
        st4(g_p22[PWR] + idx, N22.v);
    }

    // ---- p_new at left scalar (need o11, o21 only) ----
    float nl11 = 0.f, nl21 = 0.f;
    if (hasL) {
        float d11, d12, d21, d22;
        p_lane(u1L, U1c.f[0], u1DL, u2L, U2c.f[0], u2DL,
               true, hasD, taut,
               p11Lo, 0.f, p21Lo, 0.f,
               d11, d12, d21, d22);
        nl11 = d11; nl21 = d21;
    }

    // ---- p_new at up vector (need o12, o22 only) ----
    F4 NU12, NU22;
    NU12.v = NU22.v = make_float4(0,0,0,0);
    if (hasU) {
#pragma unroll
        for (int k = 0; k < 4; k++) {
            int j = j4 + k;
            float uR1 = (k < 3) ? U1u.f[k+1] : u1UR;
            float uR2 = (k < 3) ? U2u.f[k+1] : u2UR;
            float d11, d12, d21, d22;
            p_lane(U1u.f[k], uR1, U1c.f[k], U2u.f[k], uR2, U2c.f[k],
                   (j < Wd - 1), true, taut,
                   0.f, P12uo.f[k], 0.f, P22uo.f[k],
                   d11, d12, d21, d22);
            NU12.f[k] = d12; NU22.f[k] = d22;
        }
    }

    // ---- u update at center vector ----
    F4 O1, O2;
    const bool i0 = (i == 0);
#pragma unroll
    for (int k = 0; k < 4; k++) {
        int j = j4 + k;
        float l11 = (k > 0) ? N11.f[k-1] : nl11;
        float l21 = (k > 0) ? N21.f[k-1] : nl21;
        u_lane(U1c.f[k], U2c.f[k], GX.f[k], GY.f[k], RC.f[k],
               N11.f[k], l11, N12.f[k], NU12.f[k],
               N21.f[k], l21, N22.f[k], NU22.f[k],
               (j == 0), i0, ts, l_t, O1.f[k], O2.f[k]);
    }
    st4(u1w + idx, O1.v);
    st4(u2w + idx, O2.v);
}

// ============================================================================
// Schedule per quarter (u: S=scratch, D=d_out; p sets ping-pong):
//   init -> S; 9 fused launches alternate S->D->S...; last lands in D.
// ============================================================================
extern "C" void kernel_launch(void* const* d_in, const int* in_sizes, int n_in,
                              void* d_out, int out_size)
{
    const float* x = (const float*)d_in[0];
    const float* y = (const float*)d_in[1];
    const float* t = (const float*)d_in[8];
    const float* l = (const float*)d_in[9];
    const float* a = (const float*)d_in[10];

    float* ud1 = (float*)d_out;
    float* ud2 = ud1 + NPIX;

    float* us1; cudaGetSymbolAddress((void**)&us1, g_u1s);
    float* us2; cudaGetSymbolAddress((void**)&us2, g_u2s);

    const int threads = 256;
    const int blocks  = (NVQ + threads - 1) / threads;

    for (int q = 0; q < 4; ++q) {
        int off = q * QPIX;
        k_init<<<blocks, threads>>>(x, y, t, l, us1, us2, off);                              // U1 -> S
        k_pu<true,  false, 0, 0><<<blocks, threads>>>(t, l, a, us1, us2, ud1, ud2, off);     // P1,U2
        k_pu<false, false, 0, 1><<<blocks, threads>>>(t, l, a, ud1, ud2, us1, us2, off);     // P2,U3
        k_pu<false, false, 1, 0><<<blocks, threads>>>(t, l, a, us1, us2, ud1, ud2, off);     // P3,U4
        k_pu<false, false, 0, 1><<<blocks, threads>>>(t, l, a, ud1, ud2, us1, us2, off);     // P4,U5
        k_pu<false, false, 1, 0><<<blocks, threads>>>(t, l, a, us1, us2, ud1, ud2, off);     // P5,U6
        k_pu<false, false, 0, 1><<<blocks, threads>>>(t, l, a, ud1, ud2, us1, us2, off);     // P6,U7
        k_pu<false, false, 1, 0><<<blocks, threads>>>(t, l, a, us1, us2, ud1, ud2, off);     // P7,U8
        k_pu<false, false, 0, 1><<<blocks, threads>>>(t, l, a, ud1, ud2, us1, us2, off);     // P8,U9
        k_pu<false, true,  1, 0><<<blocks, threads>>>(t, l, a, us1, us2, ud1, ud2, off);     // P9,U10 -> d_out
    }
}

// round 7
// speedup vs baseline: 1.0109x; 1.0109x over previous
#include <cuda_runtime.h>

#define Wd 256
#define Hd 256
#define Bd 64
#define NPIX (Bd*Hd*Wd)
#define HIMG 32
#define HPIX (HIMG*Hd*Wd)
#define NVH  (HPIX/4)
#define SEG  16
#define EPSf 1e-12f

// ---- iteration-invariant scratch ----
__device__ __align__(16) float g_g2x[NPIX];
__device__ __align__(16) float g_g2y[NPIX];
__device__ __align__(16) float g_rc [NPIX];
// ---- double-buffered dual state ----
__device__ __align__(16) float g_p11[2][NPIX];
__device__ __align__(16) float g_p12[2][NPIX];
__device__ __align__(16) float g_p21[2][NPIX];
__device__ __align__(16) float g_p22[2][NPIX];
// ---- u scratch (ping-pongs with d_out) ----
__device__ __align__(16) float g_u1s[NPIX];
__device__ __align__(16) float g_u2s[NPIX];

union F4 { float4 v; float f[4]; };
__device__ __forceinline__ float4 ld4(const float* p) { return *reinterpret_cast<const float4*>(p); }
__device__ __forceinline__ void   st4(float* p, float4 v) { *reinterpret_cast<float4*>(p) = v; }

// u' = u + v(u) + ts*div(p)
__device__ __forceinline__ void u_lane(
    float u1, float u2, float gx, float gy, float rc,
    float p11, float p11L, float p12, float p12U,
    float p21, float p21L, float p22, float p22U,
    bool j0, bool i0, float ts, float l_t,
    float& o1, float& o2)
{
    float dx1 = j0 ? p11 : (p11 - p11L);
    float dx2 = j0 ? p21 : (p21 - p21L);
    float dy1 = i0 ? p12 : (p12 - p12U);
    float dy2 = i0 ? p22 : (p22 - p22U);
    float rho  = rc + gx * u1 + gy * u2 + EPSf;
    float grad = gx * gx + gy * gy + EPSf;
    float lg   = l_t * grad;
    float v1, v2;
    if      (rho < -lg)   { v1 =  l_t * gx; v2 =  l_t * gy; }
    else if (rho >  lg)   { v1 = -l_t * gx; v2 = -l_t * gy; }
    else if (grad > EPSf) { float s = -rho / grad; v1 = s * gx; v2 = s * gy; }
    else                  { v1 = 0.f; v2 = 0.f; }
    o1 = u1 + v1 + ts * (dx1 + dy1);
    o2 = u2 + v2 + ts * (dx2 + dy2);
}

// p' = (p + taut*grad_u) / (1 + taut*|grad_u|)
__device__ __forceinline__ void p_lane(
    float uC1, float uR1, float uD1, float uC2, float uR2, float uD2,
    bool hasR, bool hasD, float taut,
    float p11, float p12, float p21, float p22,
    float& o11, float& o12, float& o21, float& o22)
{
    float u1x = hasR ? (uR1 - uC1) : 0.f;
    float u2x = hasR ? (uR2 - uC2) : 0.f;
    float u1y = hasD ? (uD1 - uC1) : 0.f;
    float u2y = hasD ? (uD2 - uC2) : 0.f;
    float n1 = sqrtf(u1x*u1x + u1y*u1y + EPSf);
    float n2 = sqrtf(u2x*u2x + u2y*u2y + EPSf);
    float f1 = 1.0f / (1.0f + taut * n1);
    float f2 = 1.0f / (1.0f + taut * n2);
    o11 = (p11 + taut * u1x) * f1;
    o12 = (p12 + taut * u1y) * f1;
    o21 = (p21 + taut * u2x) * f2;
    o22 = (p22 + taut * u2y) * f2;
}

// ============================================================================
// Init (per half): g2x, g2y (centered grads of y, x boundary rows/cols), rc.
// ============================================================================
__global__ void __launch_bounds__(256) k_init(
    const float* __restrict__ x, const float* __restrict__ y, int off)
{
    int v = blockIdx.x * blockDim.x + threadIdx.x;
    if (v >= NVH) return;
    int il = v << 2;
    int idx = il + off;
    int j4 = il & (Wd - 1);
    int i  = (il >> 8) & (Hd - 1);

    F4 X, Y, Yu, Yd, Xu, Xd;
    X.v = ld4(x + idx);
    Y.v = ld4(y + idx);
    float yl = (j4 > 0)       ? y[idx - 1] : 0.f;
    float yr = (j4 + 4 < Wd)  ? y[idx + 4] : 0.f;
    Yu.v = (i > 0)      ? ld4(y + idx - Wd) : make_float4(0,0,0,0);
    Yd.v = (i < Hd - 1) ? ld4(y + idx + Wd) : make_float4(0,0,0,0);
    Xd.v = (i == 0)      ? ld4(x + idx + Wd) : make_float4(0,0,0,0);
    Xu.v = (i == Hd - 1) ? ld4(x + idx - Wd) : make_float4(0,0,0,0);

    F4 GX, GY, RC;
#pragma unroll
    for (int k = 0; k < 4; k++) {
        int j = j4 + k;
        float gx;
        if (j == 0)            gx = 0.5f * (X.f[1] - X.f[0]);
        else if (j == Wd - 1)  gx = 0.5f * (X.f[3] - X.f[2]);
        else {
            float yn = (k < 3) ? Y.f[k + 1] : yr;
            float yp = (k > 0) ? Y.f[k - 1] : yl;
            gx = 0.5f * (yn - yp);
        }
        float gy;
        if (i == 0)            gy = 0.5f * (Xd.f[k] - X.f[k]);
        else if (i == Hd - 1)  gy = 0.5f * (X.f[k] - Xu.f[k]);
        else                   gy = 0.5f * (Yd.f[k] - Yu.f[k]);
        GX.f[k] = gx; GY.f[k] = gy; RC.f[k] = Y.f[k] - X.f[k];
    }
    st4(g_g2x + idx, GX.v);
    st4(g_g2y + idx, GY.v);
    st4(g_rc  + idx, RC.v);
}

// ============================================================================
// One full iteration (U_k then P_k) via downward column sweep.
// Thread = one column, block = 256 cols x SEG rows of one image.
// Vertical deps via register carries; left p_old via shfl_up (lane0 loads);
// right u' via shfl_down + smem exchange at warp seams.
// FIRST: u_old = p_old = 0 (skip loads). LAST: p' dead (skip emission).
// ============================================================================
template<bool FIRST, bool LAST, int PRD, int PWR>
__global__ void __launch_bounds__(256) k_iter(
    const float* __restrict__ tp, const float* __restrict__ lp,
    const float* __restrict__ ap,
    const float* __restrict__ u1r, const float* __restrict__ u2r,
    float* __restrict__ u1w, float* __restrict__ u2w, int off)
{
    __shared__ float sx1[2][8], sx2[2][8];

    const int c    = threadIdx.x;
    const int lane = c & 31;
    const int w    = c >> 5;
    const int r0   = blockIdx.x * SEG;
    const int r1   = r0 + SEG;
    const int base = off + blockIdx.y * (Hd * Wd);

    const float ts   = tp[0];
    const float l_t  = lp[0] * ts;
    const float taut = ap[0] / ts;

    const float* __restrict__ P11r = g_p11[PRD];
    const float* __restrict__ P12r = g_p12[PRD];
    const float* __restrict__ P21r = g_p21[PRD];
    const float* __restrict__ P22r = g_p22[PRD];
    float* __restrict__ P11w = g_p11[PWR];
    float* __restrict__ P12w = g_p12[PWR];
    float* __restrict__ P21w = g_p21[PWR];
    float* __restrict__ P22w = g_p22[PWR];

    // carries
    float u1p = 0.f, u2p = 0.f, ur1p = 0.f, ur2p = 0.f;          // u'(i-1) own/right
    float pc11 = 0.f, pc12 = 0.f, pc21 = 0.f, pc22 = 0.f;        // p_old(i-1)
    float po12p = 0.f, po22p = 0.f;                              // p_old12/22(i-1)
    if (!FIRST && r0 > 0) {
        int om = base + (r0 - 1) * Wd + c;
        po12p = P12r[om]; po22p = P22r[om];
    }

    for (int i = r0; i < r1; ++i) {
        int o = base + i * Wd + c;
        float u1o = 0.f, u2o = 0.f, q11 = 0.f, q12 = 0.f, q21 = 0.f, q22 = 0.f;
        if (!FIRST) {
            u1o = u1r[o];  u2o = u2r[o];
            q11 = P11r[o]; q12 = P12r[o];
            q21 = P21r[o]; q22 = P22r[o];
        }
        float gx = g_g2x[o], gy = g_g2y[o], rc = g_rc[o];

        float l11 = 0.f, l21 = 0.f;
        if (!FIRST && lane == 0 && c > 0) { l11 = P11r[o - 1]; l21 = P21r[o - 1]; }
        float s11 = __shfl_up_sync(0xffffffffu, q11, 1);
        float s21 = __shfl_up_sync(0xffffffffu, q21, 1);
        float q11L = lane ? s11 : l11;
        float q21L = lane ? s21 : l21;

        float uc1, uc2;
        u_lane(u1o, u2o, gx, gy, rc,
               q11, q11L, q12, po12p, q21, q21L, q22, po22p,
               (c == 0), (i == 0), ts, l_t, uc1, uc2);

        // exchange right-neighbor u' (warp interior via shfl, seams via smem)
        int par = i & 1;
        if (lane == 0) { sx1[par][w] = uc1; sx2[par][w] = uc2; }
        __syncthreads();
        float t1 = __shfl_down_sync(0xffffffffu, uc1, 1);
        float t2 = __shfl_down_sync(0xffffffffu, uc2, 1);
        float ur1, ur2;
        if (lane == 31) {
            ur1 = (c < Wd - 1) ? sx1[par][w + 1] : 0.f;
            ur2 = (c < Wd - 1) ? sx2[par][w + 1] : 0.f;
        } else { ur1 = t1; ur2 = t2; }

        // emit p'(i-1): needs u'(i-1), u'(i-1,c+1), u'(i) as down-neighbor
        if (!LAST && i > r0) {
            float n11, n12, n21, n22;
            p_lane(u1p, ur1p, uc1, u2p, ur2p, uc2,
                   (c < Wd - 1), true, taut,
                   pc11, pc12, pc21, pc22, n11, n12, n21, n22);
            int om = o - Wd;
            P11w[om] = n11; P12w[om] = n12; P21w[om] = n21; P22w[om] = n22;
        }
        u1w[o] = uc1; u2w[o] = uc2;

        // rotate carries
        u1p = uc1; u2p = uc2; ur1p = ur1; ur2p = ur2;
        pc11 = q11; pc12 = q12; pc21 = q21; pc22 = q22;
        po12p = q12; po22p = q22;
    }

    // epilogue: emit p'(r1-1) (needs u'(r1) halo if r1 < H)
    if (!LAST) {
        float d1 = 0.f, d2 = 0.f;
        bool hasD = false;
        if (r1 < Hd) {
            hasD = true;
            int o = base + r1 * Wd + c;
            float u1o = 0.f, u2o = 0.f, q11 = 0.f, q12 = 0.f, q21 = 0.f, q22 = 0.f;
            if (!FIRST) {
                u1o = u1r[o];  u2o = u2r[o];
                q11 = P11r[o]; q12 = P12r[o];
                q21 = P21r[o]; q22 = P22r[o];
            }
            float gx = g_g2x[o], gy = g_g2y[o], rc = g_rc[o];
            float l11 = 0.f, l21 = 0.f;
            if (!FIRST && lane == 0 && c > 0) { l11 = P11r[o - 1]; l21 = P21r[o - 1]; }
            float s11 = __shfl_up_sync(0xffffffffu, q11, 1);
            float s21 = __shfl_up_sync(0xffffffffu, q21, 1);
            float q11L = lane ? s11 : l11;
            float q21L = lane ? s21 : l21;
            u_lane(u1o, u2o, gx, gy, rc,
                   q11, q11L, q12, po12p, q21, q21L, q22, po22p,
                   (c == 0), false, ts, l_t, d1, d2);
        }
        float n11, n12, n21, n22;
        p_lane(u1p, ur1p, d1, u2p, ur2p, d2,
               (c < Wd - 1), hasD, taut,
               pc11, pc12, pc21, pc22, n11, n12, n21, n22);
        int om = base + (r1 - 1) * Wd + c;
        P11w[om] = n11; P12w[om] = n12; P21w[om] = n21; P22w[om] = n22;
    }
}

// ============================================================================
// Schedule per half (u: S=scratch, D=d_out; p sets ping-pong):
//   init(g); iter1(FIRST)->S; iter2 S->D; ... iter10(LAST) S->D.
// ============================================================================
extern "C" void kernel_launch(void* const* d_in, const int* in_sizes, int n_in,
                              void* d_out, int out_size)
{
    const float* x = (const float*)d_in[0];
    const float* y = (const float*)d_in[1];
    const float* t = (const float*)d_in[8];
    const float* l = (const float*)d_in[9];
    const float* a = (const float*)d_in[10];

    float* ud1 = (float*)d_out;
    float* ud2 = ud1 + NPIX;

    float* us1; cudaGetSymbolAddress((void**)&us1, g_u1s);
    float* us2; cudaGetSymbolAddress((void**)&us2, g_u2s);

    const int threads = 256;
    const int blocksI = (NVH + threads - 1) / threads;
    dim3 grid(Hd / SEG, HIMG);

    for (int h = 0; h < 2; ++h) {
        int off = h * HPIX;
        k_init<<<blocksI, threads>>>(x, y, off);
        k_iter<true,  false, 0, 0><<<grid, threads>>>(t, l, a, us1, us2, us1, us2, off); // it1 -> S, p0
        k_iter<false, false, 0, 1><<<grid, threads>>>(t, l, a, us1, us2, ud1, ud2, off); // it2 S->D, p0->p1
        k_iter<false, false, 1, 0><<<grid, threads>>>(t, l, a, ud1, ud2, us1, us2, off); // it3 D->S
        k_iter<false, false, 0, 1><<<grid, threads>>>(t, l, a, us1, us2, ud1, ud2, off); // it4 S->D
        k_iter<false, false, 1, 0><<<grid, threads>>>(t, l, a, ud1, ud2, us1, us2, off); // it5 D->S
        k_iter<false, false, 0, 1><<<grid, threads>>>(t, l, a, us1, us2, ud1, ud2, off); // it6 S->D
        k_iter<false, false, 1, 0><<<grid, threads>>>(t, l, a, ud1, ud2, us1, us2, off); // it7 D->S
        k_iter<false, false, 0, 1><<<grid, threads>>>(t, l, a, us1, us2, ud1, ud2, off); // it8 S->D
        k_iter<false, false, 1, 0><<<grid, threads>>>(t, l, a, ud1, ud2, us1, us2, off); // it9 D->S
        k_iter<false, true,  0, 0><<<grid, threads>>>(t, l, a, us1, us2, ud1, ud2, off); // it10 S->D (LAST, reads p set 0)
    }
}